// round 17
// baseline (speedup 1.0000x reference)
#include <cuda_runtime.h>
#include <math.h>

#define BB   2
#define NN   1024
#define DIMM 2048
#define HH   16
#define DHH  128
#define TT   (BB*NN)    // 2048 tokens
#define HD   (HH*DHH)   // 2048
#define MAXP 16
#define NEGV -1e30f
#define QKVG_LD 8192

#define STAGES 3
#define ASTR   36                  // smem row stride (floats)
#define STAGE_A (128*ASTR)
#define STAGE_B (128*ASTR)
#define SB_NF4 (STAGES*(128+128)*ASTR*4)   // 110592 B
#define SC_SMEM (16*1024*4)                // 65536 B

// ---------------- scratch (device globals; zero-init, no allocs) ----------------
__device__ __align__(256) float g_qkvg[TT*QKVG_LD];    // q[0:2048) k[2048:4096) v[4096:6144) vg[6144:8192)
__device__ __align__(256) float g_vt[TT*HD];           // V transposed per batch: [b][c][n]
__device__ __align__(256) float g_sim [BB*HH*NN*NN];   // raw scores (QK output)
__device__ __align__(256) float g_sim2[BB*HH*NN*NN];   // mixed attn (score output)
__device__ __align__(256) float g_logits[BB*HH*NN*MAXP];
__device__ __align__(256) float g_outh[BB*HH*NN*DHH];
__device__ __align__(256) float g_hg[TT*HH];
__device__ __align__(256) float g_gated[TT*HD];
__device__ __align__(256) float g_cos[NN*DHH];
__device__ __align__(256) float g_sin[NN*DHH];
__device__ __align__(256) float g_xr[TT*DIMM];         // x rounded to tf32
__device__ __align__(256) float g_wcatT[4*DIMM*HD];    // [8192][2048]: wqT|wkT|wvT|wvgT
__device__ __align__(256) float g_woutT[HD*DIMM];

__device__ __forceinline__ float sigmoidf_(float x) { return 1.0f / (1.0f + expf(-x)); }

__device__ __forceinline__ unsigned f2tf(float x) {
    unsigned u; asm("cvt.rna.tf32.f32 %0, %1;" : "=r"(u) : "f"(x)); return u;
}
__device__ __forceinline__ float tf32r(float x) { return __uint_as_float(f2tf(x)); }

__device__ __forceinline__ void cpa16(float* dst, const float* src) {
    unsigned d = (unsigned)__cvta_generic_to_shared(dst);
    asm volatile("cp.async.cg.shared.global [%0], [%1], 16;" :: "r"(d), "l"(src));
}

__device__ __forceinline__ void ldsm4(unsigned& r0, unsigned& r1, unsigned& r2, unsigned& r3,
                                      const float* p) {
    unsigned a = (unsigned)__cvta_generic_to_shared(p);
    asm volatile("ldmatrix.sync.aligned.m8n8.x4.shared.b16 {%0,%1,%2,%3}, [%4];"
                 : "=r"(r0), "=r"(r1), "=r"(r2), "=r"(r3) : "r"(a));
}

#define MMA_TF32(cc, aa, bb)                                                     \
    asm volatile("mma.sync.aligned.m16n8k8.row.col.f32.tf32.tf32.f32 "           \
                 "{%0,%1,%2,%3},{%4,%5,%6,%7},{%8,%9},{%0,%1,%2,%3};"            \
                 : "+f"((cc)[0]), "+f"((cc)[1]), "+f"((cc)[2]), "+f"((cc)[3])    \
                 : "r"((aa)[0]), "r"((aa)[1]), "r"((aa)[2]), "r"((aa)[3]),       \
                   "r"((bb)[0]), "r"((bb)[1]))

// =====================================================================
// mma.sync tf32 GEMM. Operands pre-rounded to tf32 in gmem.
//   C[M,N] = scale * A[M,K] @ B^T  where B is stored [N][K] row-major.
// flags: 2 = causal block skip; 4 = triangular K bound; 16 = sigmoid
//        (acc+bias[col-6144]) for cols >= 6144; 32 = column-stripe swizzle.
// =====================================================================
__global__ __launch_bounds__(256, 2) void gemm_tc(
    const float* __restrict__ A, int lda, long long sAb, long long sAh,
    const float* __restrict__ B, int ldb, long long sBb, long long sBh,
    float* __restrict__ C, int ldc, long long sCb, long long sCh,
    int K, int flags, const float* __restrict__ bias, float scale)
{
    int bx = blockIdx.x, by = blockIdx.y;
    if (flags & 32) {
        int bid = by * gridDim.x + bx;
        int per = 16 * gridDim.y;
        int cg = bid / per, rem = bid - cg * per;
        by = rem >> 4;
        bx = cg * 16 + (rem & 15);
    }
    if ((flags & 2) && bx > by) return;
    int z = blockIdx.z, bz = z >> 4, hz = z & 15;
    const float* Ab = A + bz * sAb + hz * sAh;
    const float* Bb = B + bz * sBb + hz * sBh;
    float*       Cb = C + bz * sCb + hz * sCh;

    extern __shared__ float sm[];
    float* Asm = sm;
    float* Bsm = sm + STAGES * STAGE_A;

    const int tid = threadIdx.x, lane = tid & 31, wid = tid >> 5;
    const int wm = wid >> 2, wn = wid & 3;
    const int g = lane >> 2, tg = lane & 3;
    const int row0 = by * 128, col0 = bx * 128;

    float c[4][4][4];
#pragma unroll
    for (int mt = 0; mt < 4; mt++)
#pragma unroll
        for (int nt = 0; nt < 4; nt++)
#pragma unroll
            for (int e = 0; e < 4; e++) c[mt][nt][e] = 0.f;

    int kmax = K;
    if (flags & 4) { int t = row0 + 128; if (t < kmax) kmax = t; }
    const int niter = kmax >> 5;

    const int a_rl = (lane & 7) + ((lane >> 3) & 1) * 8;
    const int a_ko = (lane >> 4) * 4;
    const int b_rl = (lane & 7) + ((lane >> 4) & 1) * 8;
    const int b_ko = ((lane >> 3) & 1) * 4;
    const float* aF[4]; const float* bF[2];
#pragma unroll
    for (int mt = 0; mt < 4; mt++)
        aF[mt] = Asm + (wm * 64 + mt * 16 + a_rl) * ASTR + a_ko;
#pragma unroll
    for (int p = 0; p < 2; p++)
        bF[p] = Bsm + (wn * 32 + p * 16 + b_rl) * ASTR + b_ko;

    auto load_stage = [&](int s, int k0) {
        float* as = Asm + s * STAGE_A;
        float* bs = Bsm + s * STAGE_B;
#pragma unroll
        for (int i = 0; i < 4; i++) {
            int chunk = i * 256 + tid;
            int r = chunk >> 3, seg = (chunk & 7) << 2;
            cpa16(as + r * ASTR + seg, Ab + (size_t)(row0 + r) * lda + k0 + seg);
            cpa16(bs + r * ASTR + seg, Bb + (size_t)(col0 + r) * ldb + k0 + seg);
        }
    };

    auto compute_stage = [&](int s) {
        const int offA = s * STAGE_A, offB = s * STAGE_B;
#pragma unroll
        for (int ks = 0; ks < 4; ks++) {
            const int kb = ks * 8;
            unsigned a[4][4], b[4][2];
#pragma unroll
            for (int mt = 0; mt < 4; mt++)
                ldsm4(a[mt][0], a[mt][1], a[mt][2], a[mt][3], aF[mt] + offA + kb);
#pragma unroll
            for (int p = 0; p < 2; p++) {
                unsigned t0, t1, t2, t3;
                ldsm4(t0, t1, t2, t3, bF[p] + offB + kb);
                b[2 * p][0] = t0; b[2 * p][1] = t1;
                b[2 * p + 1][0] = t2; b[2 * p + 1][1] = t3;
            }
#pragma unroll
            for (int mt = 0; mt < 4; mt++)
#pragma unroll
                for (int nt = 0; nt < 4; nt++)
                    MMA_TF32(c[mt][nt], a[mt], b[nt]);
        }
    };

#pragma unroll
    for (int s = 0; s < STAGES - 1; s++) {
        if (s < niter) load_stage(s, s * 32);
        asm volatile("cp.async.commit_group;");
    }
    for (int it = 0; it < niter; it++) {
        asm volatile("cp.async.wait_group %0;" :: "n"(STAGES - 2));
        __syncthreads();
        int nxt = it + STAGES - 1;
        if (nxt < niter) load_stage(nxt % STAGES, nxt * 32);
        asm volatile("cp.async.commit_group;");
        compute_stage(it % STAGES);
    }

#pragma unroll
    for (int mt = 0; mt < 4; mt++) {
        int r0 = row0 + wm * 64 + mt * 16 + g;
#pragma unroll
        for (int nt = 0; nt < 4; nt++) {
            int col = col0 + wn * 32 + nt * 8 + 2 * tg;
            float v0 = c[mt][nt][0] * scale, v1 = c[mt][nt][1] * scale;
            float v2 = c[mt][nt][2] * scale, v3 = c[mt][nt][3] * scale;
            if ((flags & 16) && col >= 6144) {
                float b0 = bias[col - 6144], b1 = bias[col + 1 - 6144];
                v0 = sigmoidf_(v0 + b0);  v1 = sigmoidf_(v1 + b1);
                v2 = sigmoidf_(v2 + b0);  v3 = sigmoidf_(v3 + b1);
            }
            float2 p0; p0.x = v0; p0.y = v1;
            float2 p1; p1.x = v2; p1.y = v3;
            *(float2*)(Cb + (size_t)r0 * ldc + col)       = p0;
            *(float2*)(Cb + (size_t)(r0 + 8) * ldc + col) = p1;
        }
    }
}

// ---------------- transpose + tf32 round ----------------
__global__ void transpose_round(const float* __restrict__ in, float* __restrict__ out,
                                int rows, int cols, int ldin,
                                long long inz, long long outz) {
    __shared__ float t[32][33];
    const float* ip = in + blockIdx.z * inz;
    float* op = out + blockIdx.z * outz;
    int c0 = blockIdx.x * 32, r0 = blockIdx.y * 32;
    int tx = threadIdx.x, ty = threadIdx.y;
#pragma unroll
    for (int i = 0; i < 32; i += 8)
        t[ty + i][tx] = ip[(size_t)(r0 + ty + i) * ldin + c0 + tx];
    __syncthreads();
#pragma unroll
    for (int i = 0; i < 32; i += 8)
        op[(size_t)(c0 + ty + i) * rows + r0 + tx] = tf32r(t[tx][ty + i]);
}

// ---------------- 4-way weight transpose+round into g_wcatT ----------------
__global__ void transpose4_round(const float* __restrict__ w0, const float* __restrict__ w1,
                                 const float* __restrict__ w2, const float* __restrict__ w3) {
    __shared__ float t[32][33];
    const float* ip = (blockIdx.z == 0) ? w0 : (blockIdx.z == 1) ? w1
                    : (blockIdx.z == 2) ? w2 : w3;
    float* op = g_wcatT + (size_t)blockIdx.z * HD * DIMM;
    int c0 = blockIdx.x * 32, r0 = blockIdx.y * 32;
    int tx = threadIdx.x, ty = threadIdx.y;
#pragma unroll
    for (int i = 0; i < 32; i += 8)
        t[ty + i][tx] = ip[(size_t)(r0 + ty + i) * HD + c0 + tx];
    __syncthreads();
#pragma unroll
    for (int i = 0; i < 32; i += 8)
        op[(size_t)(c0 + ty + i) * DIMM + r0 + tx] = tf32r(t[tx][ty + i]);
}

// ---------------- tf32 round copy (x -> g_xr) ----------------
__global__ void round_copy(const float* __restrict__ in, float* __restrict__ out) {
    int i = (blockIdx.x * 256 + threadIdx.x) * 4;
    float4 v = *(const float4*)(in + i);
    v.x = tf32r(v.x); v.y = tf32r(v.y); v.z = tf32r(v.z); v.w = tf32r(v.w);
    *(float4*)(out + i) = v;
}

// ---------------- rope table ----------------
__global__ void rope_cs_kernel(const float* __restrict__ rf) {
    int idx = blockIdx.x * 256 + threadIdx.x;
    float f = rf[idx];
    g_cos[idx] = cosf(f);
    g_sin[idx] = sinf(f);
}

// ---------------- warp-per-vector L2-norm + rotary (+ CoPE logits for q) ----------
__global__ void norm_rot2_kernel(const float* __restrict__ cope) {
    int lane = threadIdx.x & 31;
    int w = blockIdx.x * 8 + (threadIdx.x >> 5);
    const int NV = TT * HH;
    int isK = (w >= NV) ? 1 : 0;
    int vec = isK ? (w - NV) : w;
    int token = vec >> 4, h = vec & 15;
    int n = token & (NN - 1), b = token >> 10;

    float* ptr = g_qkvg + (size_t)token * QKVG_LD + isK * 2048 + h * DHH + lane * 4;
    float4 v = *(float4*)ptr;
    float ss = v.x * v.x + v.y * v.y + v.z * v.z + v.w * v.w;
#pragma unroll
    for (int o = 16; o > 0; o >>= 1) ss += __shfl_xor_sync(0xffffffffu, ss, o);
    float inv = 1.0f / fmaxf(sqrtf(ss), 1e-12f);
    v.x *= inv; v.y *= inv; v.z *= inv; v.w *= inv;

    float4 cs = *(const float4*)(g_cos + n * DHH + lane * 4);
    float4 sn = *(const float4*)(g_sin + n * DHH + lane * 4);
    float4 o;
    o.x = v.x * cs.x - v.y * sn.x;
    o.y = v.y * cs.y + v.x * sn.y;
    o.z = v.z * cs.z - v.w * sn.z;
    o.w = v.w * cs.w + v.z * sn.w;
    float4 orr;
    orr.x = tf32r(o.x); orr.y = tf32r(o.y); orr.z = tf32r(o.z); orr.w = tf32r(o.w);
    *(float4*)ptr = orr;

    if (!isK) {
        float myv = 0.f;
#pragma unroll
        for (int p = 0; p < MAXP; p++) {
            float4 cp = *(const float4*)(cope + p * DHH + lane * 4);
            float pa = o.x * cp.x + o.y * cp.y + o.z * cp.z + o.w * cp.w;
#pragma unroll
            for (int off = 16; off > 0; off >>= 1)
                pa += __shfl_xor_sync(0xffffffffu, pa, off);
            if (lane == p) myv = pa;
        }
        if (lane < MAXP)
            g_logits[((size_t)(b * HH + h) * NN + n) * MAXP + lane] = myv;
    }
}

// =====================================================================
// Fused score chain, warp-per-head version.
// grid (NN, BB), 512 threads (16 warps = 16 heads), 64 KB dyn smem.
// Phase 1 (cooperative): load 16 raw score rows, pre-mix in place.
// Phase 2 (warp-local): warp h does CoPE reverse-cumsum + softmax for
//   head h with ZERO block syncs (per-chunk warp scans, ILP across 32
//   independent chains + one cross-chunk scan).
// Phase 3 (cooperative): post-mix, write g_sim2 (tf32, j<=i only; upper
//   band stays zero for the AV GEMM's triangular-K path).
// =====================================================================
__global__ __launch_bounds__(512) void score_fused2(const float* __restrict__ thp,
                                                    const float* __restrict__ tho) {
    extern __shared__ float sbuf[];                 // [16][1024]
    __shared__ float slog[256], spre[256], spost[256];
    const int i = blockIdx.x, b = blockIdx.y;
    const int tid = threadIdx.x, lane = tid & 31, hd = tid >> 5;

    if (tid < 256) {
        spre[tid] = thp[tid];
        spost[tid] = tho[tid];
        int h = tid >> 4, p = tid & 15;
        slog[tid] = g_logits[(((size_t)(b * HH + h)) * NN + i) * MAXP + p];
    }
    const int nchunk = (i + 4) >> 2;                // float4 chunks covering 0..i
    for (int idx = tid; idx < 16 * 256; idx += 512) {
        int row = idx >> 8, c4 = idx & 255;
        if (c4 < nchunk)
            cpa16(&sbuf[row * 1024 + c4 * 4],
                  g_sim + (((size_t)(b * HH + row)) * NN + i) * NN + c4 * 4);
    }
    asm volatile("cp.async.commit_group;");
    asm volatile("cp.async.wait_group 0;");
    __syncthreads();

    // ---- phase 1: pre-mix in place (column-exclusive) ----
#pragma unroll
    for (int c = 0; c < 2; c++) {
        int j = c * 512 + tid;
        if (j <= i) {
            float vals[16], outv[16];
#pragma unroll
            for (int g = 0; g < 16; g++) vals[g] = sbuf[g * 1024 + j];
#pragma unroll
            for (int h = 0; h < 16; h++) {
                float s = 0.f;
#pragma unroll
                for (int g = 0; g < 16; g++) s = fmaf(spre[h * 16 + g], vals[g], s);
                outv[h] = s;
            }
#pragma unroll
            for (int h = 0; h < 16; h++) sbuf[h * 1024 + j] = outv[h];
        }
    }
    __syncthreads();

    // ---- phase 2: warp hd handles head hd; columns j = c*32 + lane ----
    float v[32], gte[32], ex[32];
#pragma unroll
    for (int c = 0; c < 32; c++) {
        int j = c * 32 + lane;
        v[c] = sbuf[hd * 1024 + j];
        gte[c] = (j <= i) ? sigmoidf_(v[c]) : 0.f;
    }
    // per-chunk inclusive scans (independent chains) + gather chunk totals
    float csum = 0.f;
#pragma unroll
    for (int c = 0; c < 32; c++) {
        float s = gte[c];
#pragma unroll
        for (int o = 1; o < 32; o <<= 1) {
            float t = __shfl_up_sync(0xffffffffu, s, o);
            if (lane >= o) s += t;
        }
        ex[c] = s - gte[c];                        // within-chunk exclusive
        float tot = __shfl_sync(0xffffffffu, s, 31);
        if (lane == c) csum = tot;
    }
    // cross-chunk exclusive scan (lane l holds chunk l's total)
    float cs = csum;
#pragma unroll
    for (int o = 1; o < 32; o <<= 1) {
        float t = __shfl_up_sync(0xffffffffu, cs, o);
        if (lane >= o) cs += t;
    }
    float cex = cs - csum;
    float total = __shfl_sync(0xffffffffu, cs, 31);
#pragma unroll
    for (int c = 0; c < 32; c++)
        ex[c] += __shfl_sync(0xffffffffu, cex, c);

    // CoPE interp + track max
    float m = NEGV;
#pragma unroll
    for (int c = 0; c < 32; c++) {
        int j = c * 32 + lane;
        if (j <= i) {
            float pos = total - ex[c];
            pos = fminf(fmaxf(pos, 0.f), 15.0f);
            float pf = floorf(pos);
            float w = pos - pf;
            int fi = (int)pf, ci = (int)ceilf(pos);
            v[c] = v[c] + slog[hd * 16 + ci] * w + slog[hd * 16 + fi] * (1.0f - w);
        } else v[c] = NEGV;
        m = fmaxf(m, v[c]);
    }
#pragma unroll
    for (int o = 16; o > 0; o >>= 1) m = fmaxf(m, __shfl_xor_sync(0xffffffffu, m, o));
    float ls = 0.f;
#pragma unroll
    for (int c = 0; c < 32; c++) { v[c] = expf(v[c] - m); ls += v[c]; }
#pragma unroll
    for (int o = 16; o > 0; o >>= 1) ls += __shfl_xor_sync(0xffffffffu, ls, o);
    float invs = 1.0f / ls;
#pragma unroll
    for (int c = 0; c < 32; c++)
        sbuf[hd * 1024 + c * 32 + lane] = v[c] * invs;
    __syncthreads();

    // ---- phase 3: post-mix + write g_sim2 (tf32), j <= i only ----
#pragma unroll
    for (int c = 0; c < 2; c++) {
        int j = c * 512 + tid;
        if (j <= i) {
            float vals[16];
#pragma unroll
            for (int g = 0; g < 16; g++) vals[g] = sbuf[g * 1024 + j];
#pragma unroll
            for (int h = 0; h < 16; h++) {
                float s = 0.f;
#pragma unroll
                for (int g = 0; g < 16; g++) s = fmaf(spost[h * 16 + g], vals[g], s);
                g_sim2[(((size_t)(b * HH + h)) * NN + i) * NN + j] = tf32r(s);
            }
        }
    }
}

// ---------------- head gate ----------------
__global__ void hgate_kernel(const float* __restrict__ x, const float* __restrict__ wh,
                             const float* __restrict__ bh) {
    int token = blockIdx.x;
    __shared__ __align__(16) float sx[DIMM];
    int tid = threadIdx.x;
    *(float4*)&sx[tid * 4] = *(const float4*)&x[(size_t)token * DIMM + tid * 4];
    __syncthreads();
    int h = tid >> 5, lane = tid & 31;
    float s = 0.f;
    for (int e = lane; e < DIMM; e += 32) s = fmaf(sx[e], wh[e * HH + h], s);
#pragma unroll
    for (int o = 16; o > 0; o >>= 1) s += __shfl_xor_sync(0xffffffffu, s, o);
    if (lane == 0) g_hg[token * HH + h] = sigmoidf_(s + bh[h]);
}

// ---------------- apply gates, merge heads (tf32-rounded output) ----------------
__global__ void gate_mul_kernel() {
    int idx = blockIdx.x * 256 + threadIdx.x;
    int token = idx >> 11;
    int c = idx & 2047;
    int h = c >> 7, d = c & 127;
    int b = token >> 10, n = token & 1023;
    float o = g_outh[(((size_t)(b * HH + h)) * NN + n) * DHH + d];
    float vg = g_qkvg[(size_t)token * QKVG_LD + 6144 + c];
    g_gated[idx] = tf32r(o * g_hg[token * HH + h] * vg);
}

// ---------------- launch ----------------
extern "C" void kernel_launch(void* const* d_in, const int* in_sizes, int n_in,
                              void* d_out, int out_size) {
    const float* x    = (const float*)d_in[0];
    const float* rf   = (const float*)d_in[1];
    const float* wq   = (const float*)d_in[2];
    const float* wk   = (const float*)d_in[3];
    const float* wv   = (const float*)d_in[4];
    const float* cope = (const float*)d_in[5];
    const float* thp  = (const float*)d_in[6];
    const float* tho  = (const float*)d_in[7];
    const float* wvg  = (const float*)d_in[8];
    const float* bvg  = (const float*)d_in[9];
    const float* whg  = (const float*)d_in[10];
    const float* bhg  = (const float*)d_in[11];
    const float* wout = (const float*)d_in[12];
    float* out = (float*)d_out;

    cudaFuncSetAttribute(gemm_tc, cudaFuncAttributeMaxDynamicSharedMemorySize, SB_NF4);
    cudaFuncSetAttribute(score_fused2, cudaFuncAttributeMaxDynamicSharedMemorySize, SC_SMEM);

    void *pqkvg, *pvt, *psim, *psim2, *pouth, *pgated, *pxr, *pwcat, *pwoutT;
    cudaGetSymbolAddress(&pqkvg, g_qkvg);
    cudaGetSymbolAddress(&pvt, g_vt);
    cudaGetSymbolAddress(&psim, g_sim);
    cudaGetSymbolAddress(&psim2, g_sim2);
    cudaGetSymbolAddress(&pouth, g_outh);
    cudaGetSymbolAddress(&pgated, g_gated);
    cudaGetSymbolAddress(&pxr, g_xr);
    cudaGetSymbolAddress(&pwcat, g_wcatT);
    cudaGetSymbolAddress(&pwoutT, g_woutT);

    float* qkvg = (float*)pqkvg;
    float* wcat = (float*)pwcat;

    dim3 tBlk(32, 8);

    rope_cs_kernel<<<NN * DHH / 256, 256>>>(rf);

    transpose4_round<<<dim3(64, 64, 4), tBlk>>>(wq, wk, wv, wvg);
    transpose_round<<<dim3(64, 64, 1), tBlk>>>(wout, (float*)pwoutT, HD, DIMM, DIMM, 0, 0);
    round_copy<<<TT * DIMM / 1024, 256>>>(x, (float*)pxr);

    // merged QKV + value-gate projection: swizzled block order, sigmoid on vg cols
    gemm_tc<<<dim3(64, 16, 1), 256, SB_NF4>>>(
        (float*)pxr, DIMM, 0, 0, wcat, DIMM, 0, 0,
        qkvg, QKVG_LD, 0, 0, DIMM, 16 | 32, bvg, 1.f);

    norm_rot2_kernel<<<8192, 256>>>(cope);

    // V transpose per batch: g_vt[b][c][n] = tf32(qkvg[b*NN+n][4096+c])
    transpose_round<<<dim3(64, 32, BB), tBlk>>>(
        qkvg + 4096, (float*)pvt, NN, HD, QKVG_LD,
        (long long)NN * QKVG_LD, (long long)HD * NN);

    // sim = 10 * Q @ K^T (causal tiles only)
    gemm_tc<<<dim3(8, 8, BB * HH), 256, SB_NF4>>>(
        qkvg,        QKVG_LD, (long long)NN * QKVG_LD, DHH,
        qkvg + 2048, QKVG_LD, (long long)NN * QKVG_LD, DHH,
        (float*)psim, NN, 16LL * NN * NN, (long long)NN * NN,
        DHH, 2, nullptr, 10.0f);

    // fused score chain (pre-mix + CoPE softmax + post-mix), warp-per-head
    score_fused2<<<dim3(NN, BB), 512, SC_SMEM>>>(thp, tho);

    // out = attn2 @ V  (triangular K; upper band of g_sim2 is zero)
    gemm_tc<<<dim3(1, 8, BB * HH), 256, SB_NF4>>>(
        (float*)psim2, NN, 16LL * NN * NN, (long long)NN * NN,
        (float*)pvt, NN, (long long)HD * NN, (long long)DHH * NN,
        (float*)pouth, DHH, 16LL * NN * DHH, (long long)NN * DHH,
        NN, 4, nullptr, 1.f);

    hgate_kernel<<<TT, 512>>>(x, whg, bhg);
    gate_mul_kernel<<<(TT * HD) / 256, 256>>>();

    // output projection
    gemm_tc<<<dim3(16, 16, 1), 256, SB_NF4>>>(
        (float*)pgated, HD, 0, 0, (float*)pwoutT, HD, 0, 0,
        out, DIMM, 0, 0, HD, 0, nullptr, 1.f);
}